// round 1
// baseline (speedup 1.0000x reference)
#include <cuda_runtime.h>
#include <cstdint>

#define V    8      // output rows per thread
#define XPT  4      // output cols per thread (float4)
#define WIMG 1024
#define HIMG 1024

__global__ __launch_bounds__(256)
void erosion5x5_kernel(const float* __restrict__ img,
                       const float* __restrict__ filt,
                       float* __restrict__ out)
{
    const int plane = blockIdx.y;                 // fused (b, c): 0..95
    const int y0    = blockIdx.x * V;             // output row base
    const int x0    = threadIdx.x * XPT;          // 0, 4, ..., 1020

    const float* p = img + (size_t)plane * HIMG * WIMG;
    float*       q = out + (size_t)plane * HIMG * WIMG + (size_t)y0 * WIMG + x0;

    const float INF = __int_as_float(0x7f800000);

    // Negated filter in registers (uniform across threads; broadcast LDG, L1-hit).
    float nf[25];
#pragma unroll
    for (int t = 0; t < 25; ++t) nf[t] = -filt[t];

    float acc[V][XPT];
#pragma unroll
    for (int o = 0; o < V; ++o)
#pragma unroll
        for (int c = 0; c < XPT; ++c) acc[o][c] = INF;

    const bool leftEdge  = (x0 == 0);                 // need cols x0-2,x0-1 -> OOB
    const bool rightEdge = (x0 + XPT + 4 > WIMG);     // x0+4..x0+7 -> OOB (x0==1020)

    // Stream input rows y0-2 .. y0+V+1 through registers.
    // s[idx] = img[row][x0 - 4 + idx], idx 0..11 (three aligned float4 loads).
#pragma unroll
    for (int r = 0; r < V + 4; ++r) {
        const int yy = y0 - 2 + r;
        float s[12];
        if (yy >= 0 && yy < HIMG) {
            const float* row = p + (size_t)yy * WIMG + x0;
            float4 a, b, c4;
            if (leftEdge)  a  = make_float4(INF, INF, INF, INF);
            else           a  = *reinterpret_cast<const float4*>(row - 4);
            b = *reinterpret_cast<const float4*>(row);
            if (rightEdge) c4 = make_float4(INF, INF, INF, INF);
            else           c4 = *reinterpret_cast<const float4*>(row + 4);
            s[0] = a.x;  s[1] = a.y;  s[2]  = a.z;  s[3]  = a.w;
            s[4] = b.x;  s[5] = b.y;  s[6]  = b.z;  s[7]  = b.w;
            s[8] = c4.x; s[9] = c4.y; s[10] = c4.z; s[11] = c4.w;
        } else {
#pragma unroll
            for (int c = 0; c < 12; ++c) s[c] = INF;
        }

        // Input row (rel index r) feeds output row o = r - i through filter row i.
#pragma unroll
        for (int i = 0; i < 5; ++i) {
            const int o = r - i;
            if (o < 0 || o >= V) continue;   // pruned at compile time (r, i constants)
#pragma unroll
            for (int j = 0; j < 5; ++j) {
                const float w = nf[i * 5 + j];
#pragma unroll
                for (int c = 0; c < XPT; ++c) {
                    // tap col = x0 + c + j - 2  ->  s index = c + j + 2  (in [2, 9])
                    acc[o][c] = fminf(acc[o][c], s[c + j + 2] + w);
                }
            }
        }
    }

#pragma unroll
    for (int o = 0; o < V; ++o) {
        float4 v = make_float4(acc[o][0], acc[o][1], acc[o][2], acc[o][3]);
        *reinterpret_cast<float4*>(q + (size_t)o * WIMG) = v;
    }
}

extern "C" void kernel_launch(void* const* d_in, const int* in_sizes, int n_in,
                              void* d_out, int out_size)
{
    const float* img  = (const float*)d_in[0];
    const float* filt = (const float*)d_in[1];
    float*       out  = (float*)d_out;

    const int planes = in_sizes[0] / (HIMG * WIMG);   // 32*3 = 96

    dim3 block(WIMG / XPT);          // 256 threads, one row-strip of the plane
    dim3 grid(HIMG / V, planes);     // (128, 96)
    erosion5x5_kernel<<<grid, block>>>(img, filt, out);
}